// round 1
// baseline (speedup 1.0000x reference)
#include <cuda_runtime.h>
#include <math.h>

#define NN 50000
#define NE 500000
#define BATCH 10000

// ---------------- scratch (static device allocations) ----------------
__device__ float g_attr[NE * 64];   // edge_attr = [feats(32) | time_emb(32)]
__device__ float g_x[NN * 128];     // current node features
__device__ float g_q[NN * 128];
__device__ float g_k[NN * 128];
__device__ float g_v[NN * 128];
__device__ float g_out[NN * 128];   // skip + aggregated messages
__device__ float g_e[NE * 128];     // per-edge projected edge features
__device__ float g_a[NE * 4];       // per-edge per-head exp(alpha)
__device__ float g_s[NN * 4];       // per-dst per-head softmax denom

// ---------------- f32x2 packed helpers ----------------
__device__ __forceinline__ unsigned long long pack2(float x) {
    unsigned long long r;
    unsigned u = __float_as_uint(x);
    asm("mov.b64 %0, {%1, %1};" : "=l"(r) : "r"(u));
    return r;
}
__device__ __forceinline__ unsigned long long fma2(unsigned long long a,
                                                   unsigned long long b,
                                                   unsigned long long c) {
    unsigned long long d;
    asm("fma.rn.f32x2 %0, %1, %2, %3;" : "=l"(d) : "l"(a), "l"(b), "l"(c));
    return d;
}

// ---------------- edge_attr build: [feats | cos(t*tw+tb)] ----------------
__global__ void attr_kernel(const float* __restrict__ times,
                            const float* __restrict__ feats,
                            const float* __restrict__ tw,
                            const float* __restrict__ tb) {
    int idx = blockIdx.x * blockDim.x + threadIdx.x;
    if (idx >= NE * 16) return;
    int eid = idx >> 4;
    int q = idx & 15;
    if (q < 8) {
        *(float4*)&g_attr[eid * 64 + q * 4] =
            *(const float4*)&feats[eid * 32 + q * 4];
    } else {
        int j = (q - 8) * 4;
        float t = times[eid];
        float4 r;
        r.x = cosf(t * tw[j + 0] + tb[j + 0]);
        r.y = cosf(t * tw[j + 1] + tb[j + 1]);
        r.z = cosf(t * tw[j + 2] + tb[j + 2]);
        r.w = cosf(t * tw[j + 3] + tb[j + 3]);
        *(float4*)&g_attr[eid * 64 + 32 + j] = r;
    }
}

// ---------------- x = node_emb[n_id] ----------------
__global__ void gather_kernel(const int* __restrict__ n_id,
                              const float* __restrict__ emb) {
    int idx = blockIdx.x * blockDim.x + threadIdx.x;
    if (idx >= NN * 32) return;
    int i = idx >> 5;
    int c = (idx & 31) * 4;
    *(float4*)&g_x[i * 128 + c] = *(const float4*)&emb[n_id[i] * 128 + c];
}

// ---------------- generic C[M,128] = A[M,K] @ W[K,128] (+bias) ----------------
// block: 256 threads, tile 128x128, K-chunk 16, thread micro-tile 8x8 via f32x2
__global__ __launch_bounds__(256) void gemm_n128(
    const float* __restrict__ A, const float* __restrict__ W,
    const float* __restrict__ bias, float* __restrict__ C, int M, int K) {
    __shared__ float As[16][128];
    __shared__ float Bs[16][128];
    const int tid = threadIdx.x;
    const int tx = tid & 15, ty = tid >> 4;
    const int m0 = blockIdx.x * 128;
    const int rm = ty * 8, cn = tx * 8;

    unsigned long long acc[8][4];
#pragma unroll
    for (int i = 0; i < 8; i++)
#pragma unroll
        for (int j = 0; j < 4; j++) acc[i][j] = 0ULL;

    const int ar = tid >> 1, ac = (tid & 1) * 8;
    const int br = tid >> 4, bc = (tid & 15) * 8;

    for (int k0 = 0; k0 < K; k0 += 16) {
        float4 a4a = make_float4(0.f, 0.f, 0.f, 0.f);
        float4 a4b = make_float4(0.f, 0.f, 0.f, 0.f);
        int gr = m0 + ar;
        if (gr < M) {
            const float* ap = &A[gr * K + k0 + ac];
            a4a = *(const float4*)ap;
            a4b = *(const float4*)(ap + 4);
        }
        As[ac + 0][ar] = a4a.x; As[ac + 1][ar] = a4a.y;
        As[ac + 2][ar] = a4a.z; As[ac + 3][ar] = a4a.w;
        As[ac + 4][ar] = a4b.x; As[ac + 5][ar] = a4b.y;
        As[ac + 6][ar] = a4b.z; As[ac + 7][ar] = a4b.w;
        const float* wp = &W[(k0 + br) * 128 + bc];
        *(float4*)&Bs[br][bc] = *(const float4*)wp;
        *(float4*)&Bs[br][bc + 4] = *(const float4*)(wp + 4);
        __syncthreads();
#pragma unroll
        for (int kk = 0; kk < 16; kk++) {
            float4 a0 = *(const float4*)&As[kk][rm];
            float4 a1 = *(const float4*)&As[kk][rm + 4];
            ulonglong2 bb0 = *(const ulonglong2*)&Bs[kk][cn];
            ulonglong2 bb1 = *(const ulonglong2*)&Bs[kk][cn + 4];
            unsigned long long bv[4] = {bb0.x, bb0.y, bb1.x, bb1.y};
            float aval[8] = {a0.x, a0.y, a0.z, a0.w, a1.x, a1.y, a1.z, a1.w};
#pragma unroll
            for (int r = 0; r < 8; r++) {
                unsigned long long p = pack2(aval[r]);
#pragma unroll
                for (int j = 0; j < 4; j++)
                    acc[r][j] = fma2(p, bv[j], acc[r][j]);
            }
        }
        __syncthreads();
    }
    float bb[8];
#pragma unroll
    for (int j = 0; j < 8; j++) bb[j] = bias ? bias[cn + j] : 0.f;
#pragma unroll
    for (int r = 0; r < 8; r++) {
        int row = m0 + rm + r;
        if (row < M) {
            float o[8];
#pragma unroll
            for (int j = 0; j < 4; j++) {
                o[2 * j]     = __uint_as_float((unsigned)(acc[r][j])) + bb[2 * j];
                o[2 * j + 1] = __uint_as_float((unsigned)(acc[r][j] >> 32)) + bb[2 * j + 1];
            }
            float4* cp = (float4*)&C[row * 128 + cn];
            cp[0] = make_float4(o[0], o[1], o[2], o[3]);
            cp[1] = make_float4(o[4], o[5], o[6], o[7]);
        }
    }
}

// ---------------- zero ----------------
__global__ void zero_kernel(float* p, int n) {
    int i = blockIdx.x * blockDim.x + threadIdx.x;
    if (i < n) p[i] = 0.f;
}

// ---------------- per-edge alpha: a = exp(q[dst].(k[src]+e)/sqrt(32)) ------
__global__ void alpha_kernel(const int* __restrict__ ei,
                             const float* __restrict__ q,
                             const float* __restrict__ k,
                             const float* __restrict__ e,
                             float* __restrict__ a,
                             float* __restrict__ s) {
    int w = (blockIdx.x * blockDim.x + threadIdx.x) >> 5;
    int lane = threadIdx.x & 31;
    if (w >= NE) return;
    int src = ei[w], dst = ei[NE + w];
    float4 ev = *(const float4*)&e[w * 128 + lane * 4];
    float4 kv = *(const float4*)&k[src * 128 + lane * 4];
    float4 qv = *(const float4*)&q[dst * 128 + lane * 4];
    float p = qv.x * (kv.x + ev.x) + qv.y * (kv.y + ev.y) +
              qv.z * (kv.z + ev.z) + qv.w * (kv.w + ev.w);
    p += __shfl_down_sync(0xffffffffu, p, 4, 8);
    p += __shfl_down_sync(0xffffffffu, p, 2, 8);
    p += __shfl_down_sync(0xffffffffu, p, 1, 8);
    if ((lane & 7) == 0) {
        float av = expf(p * 0.17677669529663687f);  // 1/sqrt(32)
        a[w * 4 + (lane >> 3)] = av;
        atomicAdd(&s[dst * 4 + (lane >> 3)], av);
    }
}

// ---------------- per-edge aggregate: out[dst] += w * (v[src]+e) ----------
__global__ void agg_kernel(const int* __restrict__ ei,
                           const float* __restrict__ v,
                           const float* __restrict__ e,
                           const float* __restrict__ a,
                           const float* __restrict__ s,
                           float* __restrict__ out) {
    int w = (blockIdx.x * blockDim.x + threadIdx.x) >> 5;
    int lane = threadIdx.x & 31;
    if (w >= NE) return;
    int src = ei[w], dst = ei[NE + w];
    int h = lane >> 3;
    float wgt = a[w * 4 + h] / (s[dst * 4 + h] + 1e-16f);
    float4 ev = *(const float4*)&e[w * 128 + lane * 4];
    float4 vv = *(const float4*)&v[src * 128 + lane * 4];
    float* op = &out[dst * 128 + lane * 4];
    atomicAdd(op + 0, wgt * (vv.x + ev.x));
    atomicAdd(op + 1, wgt * (vv.y + ev.y));
    atomicAdd(op + 2, wgt * (vv.z + ev.z));
    atomicAdd(op + 3, wgt * (vv.w + ev.w));
}

// ---------------- relu: x = max(out, 0) ----------------
__global__ void relu_kernel(const float* __restrict__ in,
                            float* __restrict__ outp, int n) {
    int i = blockIdx.x * blockDim.x + threadIdx.x;
    if (i < n) outp[i] = fmaxf(in[i], 0.f);
}

// ---------------- final projection: y = x[:B] @ pW + pb ----------------
__global__ void proj_kernel(const float* __restrict__ x,
                            const float* __restrict__ pW,
                            const float* __restrict__ pb,
                            float* __restrict__ y) {
    int row = blockIdx.x * 8 + (threadIdx.x >> 5);
    int lane = threadIdx.x & 31;
    if (row >= BATCH) return;
    float acc = pb[lane];
    const float* xr = &x[row * 128];
#pragma unroll 8
    for (int k = 0; k < 128; k++) acc += xr[k] * pW[k * 32 + lane];
    y[row * 32 + lane] = acc;
}

// ---------------- host launch ----------------
extern "C" void kernel_launch(void* const* d_in, const int* in_sizes, int n_in,
                              void* d_out, int out_size) {
    // input layout (batch_size may or may not appear as input slot 4)
    int off = (n_in >= 28) ? 1 : 0;
    const int* n_id       = (const int*)d_in[0];
    const int* ei         = (const int*)d_in[1];
    const float* times    = (const float*)d_in[2];
    const float* feats    = (const float*)d_in[3];
    const float* node_emb = (const float*)d_in[4 + off];
    const float* tw       = (const float*)d_in[5 + off];
    const float* tb       = (const float*)d_in[6 + off];
    const float* q1W = (const float*)d_in[7 + off],  *q1b = (const float*)d_in[8 + off];
    const float* k1W = (const float*)d_in[9 + off],  *k1b = (const float*)d_in[10 + off];
    const float* v1W = (const float*)d_in[11 + off], *v1b = (const float*)d_in[12 + off];
    const float* e1W = (const float*)d_in[13 + off];
    const float* s1W = (const float*)d_in[14 + off], *s1b = (const float*)d_in[15 + off];
    const float* q2W = (const float*)d_in[16 + off], *q2b = (const float*)d_in[17 + off];
    const float* k2W = (const float*)d_in[18 + off], *k2b = (const float*)d_in[19 + off];
    const float* v2W = (const float*)d_in[20 + off], *v2b = (const float*)d_in[21 + off];
    const float* e2W = (const float*)d_in[22 + off];
    const float* s2W = (const float*)d_in[23 + off], *s2b = (const float*)d_in[24 + off];
    const float* pW  = (const float*)d_in[25 + off], *pb  = (const float*)d_in[26 + off];

    float *p_attr, *p_x, *p_q, *p_k, *p_v, *p_out, *p_e, *p_a, *p_s;
    cudaGetSymbolAddress((void**)&p_attr, g_attr);
    cudaGetSymbolAddress((void**)&p_x, g_x);
    cudaGetSymbolAddress((void**)&p_q, g_q);
    cudaGetSymbolAddress((void**)&p_k, g_k);
    cudaGetSymbolAddress((void**)&p_v, g_v);
    cudaGetSymbolAddress((void**)&p_out, g_out);
    cudaGetSymbolAddress((void**)&p_e, g_e);
    cudaGetSymbolAddress((void**)&p_a, g_a);
    cudaGetSymbolAddress((void**)&p_s, g_s);

    const int GB_N = (NN + 127) / 128;   // 391
    const int GB_E = (NE + 127) / 128;   // 3907

    attr_kernel<<<(NE * 16) / 256, 256>>>(times, feats, tw, tb);
    gather_kernel<<<(NN * 32) / 256, 256>>>(n_id, node_emb);

    // ----- layer 1 -----
    gemm_n128<<<GB_N, 256>>>(p_x, q1W, q1b, p_q, NN, 128);
    gemm_n128<<<GB_N, 256>>>(p_x, k1W, k1b, p_k, NN, 128);
    gemm_n128<<<GB_N, 256>>>(p_x, v1W, v1b, p_v, NN, 128);
    gemm_n128<<<GB_N, 256>>>(p_x, s1W, s1b, p_out, NN, 128);
    gemm_n128<<<GB_E, 256>>>(p_attr, e1W, nullptr, p_e, NE, 64);
    zero_kernel<<<(NN * 4 + 255) / 256, 256>>>(p_s, NN * 4);
    alpha_kernel<<<NE / 8, 256>>>(ei, p_q, p_k, p_e, p_a, p_s);
    agg_kernel<<<NE / 8, 256>>>(ei, p_v, p_e, p_a, p_s, p_out);
    relu_kernel<<<(NN * 128) / 256, 256>>>(p_out, p_x, NN * 128);

    // ----- layer 2 -----
    gemm_n128<<<GB_N, 256>>>(p_x, q2W, q2b, p_q, NN, 128);
    gemm_n128<<<GB_N, 256>>>(p_x, k2W, k2b, p_k, NN, 128);
    gemm_n128<<<GB_N, 256>>>(p_x, v2W, v2b, p_v, NN, 128);
    gemm_n128<<<GB_N, 256>>>(p_x, s2W, s2b, p_out, NN, 128);
    gemm_n128<<<GB_E, 256>>>(p_attr, e2W, nullptr, p_e, NE, 64);
    zero_kernel<<<(NN * 4 + 255) / 256, 256>>>(p_s, NN * 4);
    alpha_kernel<<<NE / 8, 256>>>(ei, p_q, p_k, p_e, p_a, p_s);
    agg_kernel<<<NE / 8, 256>>>(ei, p_v, p_e, p_a, p_s, p_out);

    // ----- projection -----
    proj_kernel<<<(BATCH + 7) / 8, 256>>>(p_out, pW, pb, (float*)d_out);
}

// round 2
// speedup vs baseline: 1.7938x; 1.7938x over previous
#include <cuda_runtime.h>
#include <math.h>

#define NN 50000
#define NE 500000
#define BATCH 10000

// ---------------- scratch ----------------
__device__ float g_attr[NE * 64];
__device__ float g_x[NN * 128];
__device__ float g_q[NN * 128];
__device__ float g_k[NN * 128];
__device__ float g_v[NN * 128];
__device__ float g_skip[NN * 128];
__device__ float g_acc[NN * 128];
__device__ float g_e[NE * 128];
__device__ float g_s[NN * 4];
__device__ float g_h2[NN * 128];   // layer2 output

__device__ __forceinline__ unsigned f2tf(float f) {
    unsigned u;
    asm("cvt.rna.tf32.f32 %0, %1;" : "=r"(u) : "f"(f));
    return u;
}

// ---------------- edge_attr build ----------------
__global__ void attr_kernel(const float* __restrict__ times,
                            const float* __restrict__ feats,
                            const float* __restrict__ tw,
                            const float* __restrict__ tb) {
    int idx = blockIdx.x * blockDim.x + threadIdx.x;
    if (idx >= NE * 16) return;
    int eid = idx >> 4;
    int q = idx & 15;
    if (q < 8) {
        *(float4*)&g_attr[eid * 64 + q * 4] =
            *(const float4*)&feats[eid * 32 + q * 4];
    } else {
        int j = (q - 8) * 4;
        float t = times[eid];
        float4 r;
        r.x = cosf(t * tw[j + 0] + tb[j + 0]);
        r.y = cosf(t * tw[j + 1] + tb[j + 1]);
        r.z = cosf(t * tw[j + 2] + tb[j + 2]);
        r.w = cosf(t * tw[j + 3] + tb[j + 3]);
        *(float4*)&g_attr[eid * 64 + 32 + j] = r;
    }
}

// ---------------- x = node_emb[n_id] ----------------
__global__ void gather_kernel(const int* __restrict__ n_id,
                              const float* __restrict__ emb) {
    int idx = blockIdx.x * blockDim.x + threadIdx.x;
    if (idx >= NN * 32) return;
    int i = idx >> 5;
    int c = (idx & 31) * 4;
    *(float4*)&g_x[i * 128 + c] = *(const float4*)&emb[n_id[i] * 128 + c];
}

// ---------------- TF32 tensor-core GEMM: C[M,128] = A[M,K] @ W[K,128] + b ---
// block 256 thr = 8 warps; tile 128x128; BK=32; warp tile 32x64 via m16n8k8
__global__ __launch_bounds__(256) void gemm_tf32(
    const float* __restrict__ A, const float* __restrict__ W,
    const float* __restrict__ bias, float* __restrict__ C, int M, int K) {
    __shared__ unsigned As[32][136];   // [k][m], pad 8 -> conflict-free frags
    __shared__ unsigned Bs[32][136];   // [k][n]
    const int tid = threadIdx.x;
    const int lane = tid & 31, wid = tid >> 5;
    const int wm = (wid & 3) * 32, wn = (wid >> 2) * 64;
    const int g = lane >> 2, t = lane & 3;
    const int m0 = blockIdx.x * 128;

    float acc[2][8][4];
#pragma unroll
    for (int i = 0; i < 2; i++)
#pragma unroll
        for (int j = 0; j < 8; j++)
#pragma unroll
            for (int c = 0; c < 4; c++) acc[i][j][c] = 0.f;

    const int arow = tid >> 1;          // 0..127
    const int acol = (tid & 1) * 16;    // 0 / 16
    const int brow = tid >> 3;          // 0..31
    const int bcol = (tid & 7) * 16;

    for (int k0 = 0; k0 < K; k0 += 32) {
        int gr = m0 + arow;
        const float* ap = &A[(size_t)gr * K + k0 + acol];
#pragma unroll
        for (int c = 0; c < 4; c++) {
            float4 v = (gr < M) ? *(const float4*)(ap + c * 4)
                                : make_float4(0.f, 0.f, 0.f, 0.f);
            As[acol + c * 4 + 0][arow] = f2tf(v.x);
            As[acol + c * 4 + 1][arow] = f2tf(v.y);
            As[acol + c * 4 + 2][arow] = f2tf(v.z);
            As[acol + c * 4 + 3][arow] = f2tf(v.w);
        }
        const float* wp = &W[(size_t)(k0 + brow) * 128 + bcol];
#pragma unroll
        for (int c = 0; c < 4; c++) {
            float4 v = *(const float4*)(wp + c * 4);
            Bs[brow][bcol + c * 4 + 0] = f2tf(v.x);
            Bs[brow][bcol + c * 4 + 1] = f2tf(v.y);
            Bs[brow][bcol + c * 4 + 2] = f2tf(v.z);
            Bs[brow][bcol + c * 4 + 3] = f2tf(v.w);
        }
        __syncthreads();
#pragma unroll
        for (int kk = 0; kk < 32; kk += 8) {
            unsigned af[2][4];
#pragma unroll
            for (int i = 0; i < 2; i++) {
                af[i][0] = As[kk + t][wm + i * 16 + g];
                af[i][1] = As[kk + t][wm + i * 16 + g + 8];
                af[i][2] = As[kk + t + 4][wm + i * 16 + g];
                af[i][3] = As[kk + t + 4][wm + i * 16 + g + 8];
            }
            unsigned bf[8][2];
#pragma unroll
            for (int j = 0; j < 8; j++) {
                bf[j][0] = Bs[kk + t][wn + j * 8 + g];
                bf[j][1] = Bs[kk + t + 4][wn + j * 8 + g];
            }
#pragma unroll
            for (int i = 0; i < 2; i++)
#pragma unroll
                for (int j = 0; j < 8; j++) {
                    float* c = acc[i][j];
                    asm volatile(
                        "mma.sync.aligned.m16n8k8.row.col.f32.tf32.tf32.f32 "
                        "{%0,%1,%2,%3}, {%4,%5,%6,%7}, {%8,%9}, {%0,%1,%2,%3};"
                        : "+f"(c[0]), "+f"(c[1]), "+f"(c[2]), "+f"(c[3])
                        : "r"(af[i][0]), "r"(af[i][1]), "r"(af[i][2]),
                          "r"(af[i][3]), "r"(bf[j][0]), "r"(bf[j][1]));
                }
        }
        __syncthreads();
    }
#pragma unroll
    for (int i = 0; i < 2; i++) {
        int r0 = m0 + wm + i * 16 + g;
#pragma unroll
        for (int j = 0; j < 8; j++) {
            int col = wn + j * 8 + t * 2;
            float b0 = bias ? bias[col] : 0.f;
            float b1 = bias ? bias[col + 1] : 0.f;
            if (r0 < M)
                *(float2*)&C[(size_t)r0 * 128 + col] =
                    make_float2(acc[i][j][0] + b0, acc[i][j][1] + b1);
            if (r0 + 8 < M)
                *(float2*)&C[(size_t)(r0 + 8) * 128 + col] =
                    make_float2(acc[i][j][2] + b0, acc[i][j][3] + b1);
        }
    }
}

// ---------------- zero ----------------
__global__ void zero_kernel(float* p, int n) {
    int i = blockIdx.x * blockDim.x + threadIdx.x;
    if (i < n) p[i] = 0.f;
}

// ------- fused edge pass: a=exp(q[dst].(k[src]+e)/sqrt32);
//         s[dst,h]+=a;  acc[dst,:]+=a*(v[src]+e)  (unnormalized) -------
__global__ void edge_kernel(const int* __restrict__ ei,
                            const float* __restrict__ q,
                            const float* __restrict__ k,
                            const float* __restrict__ v,
                            const float* __restrict__ e,
                            float* __restrict__ s,
                            float* __restrict__ acc) {
    int w = (blockIdx.x * blockDim.x + threadIdx.x) >> 5;
    int lane = threadIdx.x & 31;
    if (w >= NE) return;
    int src = ei[w], dst = ei[NE + w];
    float4 ev = *(const float4*)&e[(size_t)w * 128 + lane * 4];
    float4 kv = *(const float4*)&k[(size_t)src * 128 + lane * 4];
    float4 qv = *(const float4*)&q[(size_t)dst * 128 + lane * 4];
    float4 vv = *(const float4*)&v[(size_t)src * 128 + lane * 4];
    float p = qv.x * (kv.x + ev.x) + qv.y * (kv.y + ev.y) +
              qv.z * (kv.z + ev.z) + qv.w * (kv.w + ev.w);
    p += __shfl_xor_sync(0xffffffffu, p, 1, 8);
    p += __shfl_xor_sync(0xffffffffu, p, 2, 8);
    p += __shfl_xor_sync(0xffffffffu, p, 4, 8);
    float a = expf(p * 0.17677669529663687f);   // 1/sqrt(32)
    if ((lane & 7) == 0)
        atomicAdd(&s[dst * 4 + (lane >> 3)], a);
    float4 m = make_float4(a * (vv.x + ev.x), a * (vv.y + ev.y),
                           a * (vv.z + ev.z), a * (vv.w + ev.w));
    float* op = &acc[(size_t)dst * 128 + lane * 4];
    asm volatile("red.global.add.v4.f32 [%0], {%1,%2,%3,%4};"
                 :: "l"(op), "f"(m.x), "f"(m.y), "f"(m.z), "f"(m.w)
                 : "memory");
}

// ------- normalize: out = skip + acc/s (+relu) -------
__global__ void norm_kernel(const float* __restrict__ skip,
                            const float* __restrict__ acc,
                            const float* __restrict__ s,
                            float* __restrict__ outp, int do_relu) {
    int idx = blockIdx.x * blockDim.x + threadIdx.x;
    if (idx >= NN * 32) return;
    int n = idx >> 5, c4 = idx & 31;
    float sv = s[n * 4 + (c4 >> 3)] + 1e-16f;
    float inv = 1.f / sv;
    float4 a = *(const float4*)&acc[n * 128 + c4 * 4];
    float4 kk = *(const float4*)&skip[n * 128 + c4 * 4];
    float4 o = make_float4(kk.x + a.x * inv, kk.y + a.y * inv,
                           kk.z + a.z * inv, kk.w + a.w * inv);
    if (do_relu) {
        o.x = fmaxf(o.x, 0.f); o.y = fmaxf(o.y, 0.f);
        o.z = fmaxf(o.z, 0.f); o.w = fmaxf(o.w, 0.f);
    }
    *(float4*)&outp[n * 128 + c4 * 4] = o;
}

// ---------------- final projection ----------------
__global__ void proj_kernel(const float* __restrict__ x,
                            const float* __restrict__ pW,
                            const float* __restrict__ pb,
                            float* __restrict__ y) {
    int row = blockIdx.x * 8 + (threadIdx.x >> 5);
    int lane = threadIdx.x & 31;
    if (row >= BATCH) return;
    float acc = pb[lane];
    const float* xr = &x[row * 128];
#pragma unroll 8
    for (int k = 0; k < 128; k++) acc += xr[k] * pW[k * 32 + lane];
    y[row * 32 + lane] = acc;
}

// ---------------- host launch ----------------
extern "C" void kernel_launch(void* const* d_in, const int* in_sizes, int n_in,
                              void* d_out, int out_size) {
    int off = (n_in >= 28) ? 1 : 0;
    const int* n_id       = (const int*)d_in[0];
    const int* ei         = (const int*)d_in[1];
    const float* times    = (const float*)d_in[2];
    const float* feats    = (const float*)d_in[3];
    const float* node_emb = (const float*)d_in[4 + off];
    const float* tw       = (const float*)d_in[5 + off];
    const float* tb       = (const float*)d_in[6 + off];
    const float* q1W = (const float*)d_in[7 + off],  *q1b = (const float*)d_in[8 + off];
    const float* k1W = (const float*)d_in[9 + off],  *k1b = (const float*)d_in[10 + off];
    const float* v1W = (const float*)d_in[11 + off], *v1b = (const float*)d_in[12 + off];
    const float* e1W = (const float*)d_in[13 + off];
    const float* s1W = (const float*)d_in[14 + off], *s1b = (const float*)d_in[15 + off];
    const float* q2W = (const float*)d_in[16 + off], *q2b = (const float*)d_in[17 + off];
    const float* k2W = (const float*)d_in[18 + off], *k2b = (const float*)d_in[19 + off];
    const float* v2W = (const float*)d_in[20 + off], *v2b = (const float*)d_in[21 + off];
    const float* e2W = (const float*)d_in[22 + off];
    const float* s2W = (const float*)d_in[23 + off], *s2b = (const float*)d_in[24 + off];
    const float* pW  = (const float*)d_in[25 + off], *pb  = (const float*)d_in[26 + off];

    float *p_attr, *p_x, *p_q, *p_k, *p_v, *p_skip, *p_acc, *p_e, *p_s, *p_h2;
    cudaGetSymbolAddress((void**)&p_attr, g_attr);
    cudaGetSymbolAddress((void**)&p_x, g_x);
    cudaGetSymbolAddress((void**)&p_q, g_q);
    cudaGetSymbolAddress((void**)&p_k, g_k);
    cudaGetSymbolAddress((void**)&p_v, g_v);
    cudaGetSymbolAddress((void**)&p_skip, g_skip);
    cudaGetSymbolAddress((void**)&p_acc, g_acc);
    cudaGetSymbolAddress((void**)&p_e, g_e);
    cudaGetSymbolAddress((void**)&p_s, g_s);
    cudaGetSymbolAddress((void**)&p_h2, g_h2);

    const int GB_N = (NN + 127) / 128;    // 391
    const int GB_E = (NE + 127) / 128;    // 3907

    attr_kernel<<<(NE * 16) / 256, 256>>>(times, feats, tw, tb);
    gather_kernel<<<(NN * 32) / 256, 256>>>(n_id, node_emb);

    // ----- layer 1 -----
    gemm_tf32<<<GB_N, 256>>>(p_x, q1W, q1b, p_q, NN, 128);
    gemm_tf32<<<GB_N, 256>>>(p_x, k1W, k1b, p_k, NN, 128);
    gemm_tf32<<<GB_N, 256>>>(p_x, v1W, v1b, p_v, NN, 128);
    gemm_tf32<<<GB_N, 256>>>(p_x, s1W, s1b, p_skip, NN, 128);
    gemm_tf32<<<GB_E, 256>>>(p_attr, e1W, nullptr, p_e, NE, 64);
    zero_kernel<<<(NN * 4 + 255) / 256, 256>>>(p_s, NN * 4);
    zero_kernel<<<(NN * 128 + 255) / 256, 256>>>(p_acc, NN * 128);
    edge_kernel<<<NE / 8, 256>>>(ei, p_q, p_k, p_v, p_e, p_s, p_acc);
    norm_kernel<<<(NN * 32 + 255) / 256, 256>>>(p_skip, p_acc, p_s, p_x, 1);

    // ----- layer 2 -----
    gemm_tf32<<<GB_N, 256>>>(p_x, q2W, q2b, p_q, NN, 128);
    gemm_tf32<<<GB_N, 256>>>(p_x, k2W, k2b, p_k, NN, 128);
    gemm_tf32<<<GB_N, 256>>>(p_x, v2W, v2b, p_v, NN, 128);
    gemm_tf32<<<GB_N, 256>>>(p_x, s2W, s2b, p_skip, NN, 128);
    gemm_tf32<<<GB_E, 256>>>(p_attr, e2W, nullptr, p_e, NE, 64);
    zero_kernel<<<(NN * 4 + 255) / 256, 256>>>(p_s, NN * 4);
    zero_kernel<<<(NN * 128 + 255) / 256, 256>>>(p_acc, NN * 128);
    edge_kernel<<<NE / 8, 256>>>(ei, p_q, p_k, p_v, p_e, p_s, p_acc);
    norm_kernel<<<(NN * 32 + 255) / 256, 256>>>(p_skip, p_acc, p_s, p_h2, 0);

    // ----- projection -----
    proj_kernel<<<(BATCH + 7) / 8, 256>>>(p_h2, pW, pb, (float*)d_out);
}

// round 3
// speedup vs baseline: 1.9641x; 1.0949x over previous
#include <cuda_runtime.h>
#include <cuda_fp16.h>
#include <math.h>

#define NN 50000
#define NE 500000
#define BATCH 10000

// ---------------- scratch ----------------
__device__ float g_attr[NE * 64];
__device__ float g_x[NN * 128];
__device__ float g_nqkvs[NN * 512];   // [q | k | v | skip] per node
__device__ float g_acc[NN * 128];
__device__ __half g_e[NE * 128];
__device__ float g_s[NN * 4];
__device__ float g_h2[NN * 128];
__device__ float g_Wc[128 * 512];     // concatenated weights
__device__ float g_bc[512];           // concatenated biases

__device__ __forceinline__ unsigned f2tf(float f) {
    unsigned u;
    asm("cvt.rna.tf32.f32 %0, %1;" : "=r"(u) : "f"(f));
    return u;
}

// ---------------- edge_attr build ----------------
__global__ void attr_kernel(const float* __restrict__ times,
                            const float* __restrict__ feats,
                            const float* __restrict__ tw,
                            const float* __restrict__ tb) {
    int idx = blockIdx.x * blockDim.x + threadIdx.x;
    if (idx >= NE * 16) return;
    int eid = idx >> 4;
    int q = idx & 15;
    if (q < 8) {
        *(float4*)&g_attr[eid * 64 + q * 4] =
            *(const float4*)&feats[eid * 32 + q * 4];
    } else {
        int j = (q - 8) * 4;
        float t = times[eid];
        float4 r;
        r.x = cosf(t * tw[j + 0] + tb[j + 0]);
        r.y = cosf(t * tw[j + 1] + tb[j + 1]);
        r.z = cosf(t * tw[j + 2] + tb[j + 2]);
        r.w = cosf(t * tw[j + 3] + tb[j + 3]);
        *(float4*)&g_attr[eid * 64 + 32 + j] = r;
    }
}

// ---------------- x = node_emb[n_id] ----------------
__global__ void gather_kernel(const int* __restrict__ n_id,
                              const float* __restrict__ emb) {
    int idx = blockIdx.x * blockDim.x + threadIdx.x;
    if (idx >= NN * 32) return;
    int i = idx >> 5;
    int c = (idx & 31) * 4;
    *(float4*)&g_x[i * 128 + c] = *(const float4*)&emb[n_id[i] * 128 + c];
}

// ---------------- concat 4x [128,128] weights -> [128,512] ----------------
__global__ void concat_w(const float* __restrict__ qW, const float* __restrict__ kW,
                         const float* __restrict__ vW, const float* __restrict__ sW,
                         const float* __restrict__ qb, const float* __restrict__ kb,
                         const float* __restrict__ vb, const float* __restrict__ sb) {
    int i = blockIdx.x * blockDim.x + threadIdx.x;
    if (i >= 128 * 512) return;
    int k = i >> 9, c = i & 511;
    int which = c >> 7, cc = c & 127;
    const float* W = which == 0 ? qW : which == 1 ? kW : which == 2 ? vW : sW;
    g_Wc[i] = W[k * 128 + cc];
    if (k == 0) {
        const float* b = which == 0 ? qb : which == 1 ? kb : which == 2 ? vb : sb;
        g_bc[c] = b[cc];
    }
}

// ---------------- TF32 tensor-core GEMM ----------------
// C[M,N] = A[M,K] @ W[K,N] + b ; block tile 128x128, BK=32, 256 thr
template <typename OutT>
__global__ __launch_bounds__(256) void gemm_tf32(
    const float* __restrict__ A, const float* __restrict__ W,
    const float* __restrict__ bias, OutT* __restrict__ C,
    int M, int K, int N) {
    __shared__ unsigned As[32][136];
    __shared__ unsigned Bs[32][136];
    const int tid = threadIdx.x;
    const int lane = tid & 31, wid = tid >> 5;
    const int wm = (wid & 3) * 32, wn = (wid >> 2) * 64;
    const int g = lane >> 2, t = lane & 3;
    const int m0 = blockIdx.x * 128;
    const int n0 = blockIdx.y * 128;

    float acc[2][8][4];
#pragma unroll
    for (int i = 0; i < 2; i++)
#pragma unroll
        for (int j = 0; j < 8; j++)
#pragma unroll
            for (int c = 0; c < 4; c++) acc[i][j][c] = 0.f;

    const int arow = tid >> 1;
    const int acol = (tid & 1) * 16;
    const int brow = tid >> 3;
    const int bcol = (tid & 7) * 16;

    for (int k0 = 0; k0 < K; k0 += 32) {
        int gr = m0 + arow;
        const float* ap = &A[(size_t)gr * K + k0 + acol];
#pragma unroll
        for (int c = 0; c < 4; c++) {
            float4 v = (gr < M) ? *(const float4*)(ap + c * 4)
                                : make_float4(0.f, 0.f, 0.f, 0.f);
            As[acol + c * 4 + 0][arow] = f2tf(v.x);
            As[acol + c * 4 + 1][arow] = f2tf(v.y);
            As[acol + c * 4 + 2][arow] = f2tf(v.z);
            As[acol + c * 4 + 3][arow] = f2tf(v.w);
        }
        const float* wp = &W[(size_t)(k0 + brow) * N + n0 + bcol];
#pragma unroll
        for (int c = 0; c < 4; c++) {
            float4 v = *(const float4*)(wp + c * 4);
            Bs[brow][bcol + c * 4 + 0] = f2tf(v.x);
            Bs[brow][bcol + c * 4 + 1] = f2tf(v.y);
            Bs[brow][bcol + c * 4 + 2] = f2tf(v.z);
            Bs[brow][bcol + c * 4 + 3] = f2tf(v.w);
        }
        __syncthreads();
#pragma unroll
        for (int kk = 0; kk < 32; kk += 8) {
            unsigned af[2][4];
#pragma unroll
            for (int i = 0; i < 2; i++) {
                af[i][0] = As[kk + t][wm + i * 16 + g];
                af[i][1] = As[kk + t][wm + i * 16 + g + 8];
                af[i][2] = As[kk + t + 4][wm + i * 16 + g];
                af[i][3] = As[kk + t + 4][wm + i * 16 + g + 8];
            }
            unsigned bf[8][2];
#pragma unroll
            for (int j = 0; j < 8; j++) {
                bf[j][0] = Bs[kk + t][wn + j * 8 + g];
                bf[j][1] = Bs[kk + t + 4][wn + j * 8 + g];
            }
#pragma unroll
            for (int i = 0; i < 2; i++)
#pragma unroll
                for (int j = 0; j < 8; j++) {
                    float* c = acc[i][j];
                    asm volatile(
                        "mma.sync.aligned.m16n8k8.row.col.f32.tf32.tf32.f32 "
                        "{%0,%1,%2,%3}, {%4,%5,%6,%7}, {%8,%9}, {%0,%1,%2,%3};"
                        : "+f"(c[0]), "+f"(c[1]), "+f"(c[2]), "+f"(c[3])
                        : "r"(af[i][0]), "r"(af[i][1]), "r"(af[i][2]),
                          "r"(af[i][3]), "r"(bf[j][0]), "r"(bf[j][1]));
                }
        }
        __syncthreads();
    }
#pragma unroll
    for (int i = 0; i < 2; i++) {
        int r0 = m0 + wm + i * 16 + g;
#pragma unroll
        for (int j = 0; j < 8; j++) {
            int col = n0 + wn + j * 8 + t * 2;
            float b0 = bias ? bias[col] : 0.f;
            float b1 = bias ? bias[col + 1] : 0.f;
#pragma unroll
            for (int rr = 0; rr < 2; rr++) {
                int row = r0 + rr * 8;
                if (row < M) {
                    float o0 = acc[i][j][rr * 2 + 0] + b0;
                    float o1 = acc[i][j][rr * 2 + 1] + b1;
                    if constexpr (sizeof(OutT) == 2) {
                        *(__half2*)&C[(size_t)row * N + col] =
                            __floats2half2_rn(o0, o1);
                    } else {
                        *(float2*)&C[(size_t)row * N + col] = make_float2(o0, o1);
                    }
                }
            }
        }
    }
}

// ---------------- zero ----------------
__global__ void zero_kernel(float* p, int n) {
    int i = blockIdx.x * blockDim.x + threadIdx.x;
    if (i < n) p[i] = 0.f;
}

// ------- fused edge pass: a = exp(q[dst].(k[src]+e)/sqrt32);
//         s[dst,h]+=a;  acc[dst,:]+=a*(v[src]+e) -------
__global__ void edge_kernel(const int* __restrict__ ei,
                            const float* __restrict__ nqkvs,
                            const __half* __restrict__ e,
                            float* __restrict__ s,
                            float* __restrict__ acc) {
    int w = (blockIdx.x * blockDim.x + threadIdx.x) >> 5;
    int lane = threadIdx.x & 31;
    if (w >= NE) return;
    int src = ei[w], dst = ei[NE + w];
    uint2 eraw = *(const uint2*)&e[(size_t)w * 128 + lane * 4];
    float2 e01 = __half22float2(*reinterpret_cast<__half2*>(&eraw.x));
    float2 e23 = __half22float2(*reinterpret_cast<__half2*>(&eraw.y));
    float4 qv = *(const float4*)&nqkvs[(size_t)dst * 512 + lane * 4];
    float4 kv = *(const float4*)&nqkvs[(size_t)src * 512 + 128 + lane * 4];
    float4 vv = *(const float4*)&nqkvs[(size_t)src * 512 + 256 + lane * 4];
    float p = qv.x * (kv.x + e01.x) + qv.y * (kv.y + e01.y) +
              qv.z * (kv.z + e23.x) + qv.w * (kv.w + e23.y);
    p += __shfl_xor_sync(0xffffffffu, p, 1, 8);
    p += __shfl_xor_sync(0xffffffffu, p, 2, 8);
    p += __shfl_xor_sync(0xffffffffu, p, 4, 8);
    float a = expf(p * 0.17677669529663687f);   // 1/sqrt(32)
    if ((lane & 7) == 0)
        atomicAdd(&s[dst * 4 + (lane >> 3)], a);
    float4 m = make_float4(a * (vv.x + e01.x), a * (vv.y + e01.y),
                           a * (vv.z + e23.x), a * (vv.w + e23.y));
    float* op = &acc[(size_t)dst * 128 + lane * 4];
    asm volatile("red.global.add.v4.f32 [%0], {%1,%2,%3,%4};"
                 :: "l"(op), "f"(m.x), "f"(m.y), "f"(m.z), "f"(m.w)
                 : "memory");
}

// ------- normalize: out = skip + acc/s (+relu) -------
__global__ void norm_kernel(const float* __restrict__ nqkvs,
                            const float* __restrict__ acc,
                            const float* __restrict__ s,
                            float* __restrict__ outp, int do_relu) {
    int idx = blockIdx.x * blockDim.x + threadIdx.x;
    if (idx >= NN * 32) return;
    int n = idx >> 5, c4 = idx & 31;
    float inv = 1.f / (s[n * 4 + (c4 >> 3)] + 1e-16f);
    float4 a = *(const float4*)&acc[n * 128 + c4 * 4];
    float4 kk = *(const float4*)&nqkvs[(size_t)n * 512 + 384 + c4 * 4];
    float4 o = make_float4(kk.x + a.x * inv, kk.y + a.y * inv,
                           kk.z + a.z * inv, kk.w + a.w * inv);
    if (do_relu) {
        o.x = fmaxf(o.x, 0.f); o.y = fmaxf(o.y, 0.f);
        o.z = fmaxf(o.z, 0.f); o.w = fmaxf(o.w, 0.f);
    }
    *(float4*)&outp[n * 128 + c4 * 4] = o;
}

// ---------------- final projection ----------------
__global__ void proj_kernel(const float* __restrict__ x,
                            const float* __restrict__ pW,
                            const float* __restrict__ pb,
                            float* __restrict__ y) {
    int row = blockIdx.x * 8 + (threadIdx.x >> 5);
    int lane = threadIdx.x & 31;
    if (row >= BATCH) return;
    float acc = pb[lane];
    const float* xr = &x[row * 128];
#pragma unroll 8
    for (int k = 0; k < 128; k++) acc += xr[k] * pW[k * 32 + lane];
    y[row * 32 + lane] = acc;
}

// ---------------- host launch ----------------
extern "C" void kernel_launch(void* const* d_in, const int* in_sizes, int n_in,
                              void* d_out, int out_size) {
    int off = (n_in >= 28) ? 1 : 0;
    const int* n_id       = (const int*)d_in[0];
    const int* ei         = (const int*)d_in[1];
    const float* times    = (const float*)d_in[2];
    const float* feats    = (const float*)d_in[3];
    const float* node_emb = (const float*)d_in[4 + off];
    const float* tw       = (const float*)d_in[5 + off];
    const float* tb       = (const float*)d_in[6 + off];
    const float* q1W = (const float*)d_in[7 + off],  *q1b = (const float*)d_in[8 + off];
    const float* k1W = (const float*)d_in[9 + off],  *k1b = (const float*)d_in[10 + off];
    const float* v1W = (const float*)d_in[11 + off], *v1b = (const float*)d_in[12 + off];
    const float* e1W = (const float*)d_in[13 + off];
    const float* s1W = (const float*)d_in[14 + off], *s1b = (const float*)d_in[15 + off];
    const float* q2W = (const float*)d_in[16 + off], *q2b = (const float*)d_in[17 + off];
    const float* k2W = (const float*)d_in[18 + off], *k2b = (const float*)d_in[19 + off];
    const float* v2W = (const float*)d_in[20 + off], *v2b = (const float*)d_in[21 + off];
    const float* e2W = (const float*)d_in[22 + off];
    const float* s2W = (const float*)d_in[23 + off], *s2b = (const float*)d_in[24 + off];
    const float* pW  = (const float*)d_in[25 + off], *pb  = (const float*)d_in[26 + off];

    float *p_attr, *p_x, *p_nq, *p_acc, *p_s, *p_h2, *p_Wc, *p_bc;
    __half* p_e;
    cudaGetSymbolAddress((void**)&p_attr, g_attr);
    cudaGetSymbolAddress((void**)&p_x, g_x);
    cudaGetSymbolAddress((void**)&p_nq, g_nqkvs);
    cudaGetSymbolAddress((void**)&p_acc, g_acc);
    cudaGetSymbolAddress((void**)&p_e, g_e);
    cudaGetSymbolAddress((void**)&p_s, g_s);
    cudaGetSymbolAddress((void**)&p_h2, g_h2);
    cudaGetSymbolAddress((void**)&p_Wc, g_Wc);
    cudaGetSymbolAddress((void**)&p_bc, g_bc);

    const int GB_N = (NN + 127) / 128;    // 391
    const int GB_E = (NE + 127) / 128;    // 3907

    attr_kernel<<<(NE * 16) / 256, 256>>>(times, feats, tw, tb);
    gather_kernel<<<(NN * 32) / 256, 256>>>(n_id, node_emb);

    // ----- layer 1 -----
    concat_w<<<(128 * 512) / 256, 256>>>(q1W, k1W, v1W, s1W, q1b, k1b, v1b, s1b);
    gemm_tf32<float><<<dim3(GB_N, 4), 256>>>(p_x, p_Wc, p_bc, p_nq, NN, 128, 512);
    gemm_tf32<__half><<<dim3(GB_E, 1), 256>>>(p_attr, e1W, nullptr, p_e, NE, 64, 128);
    zero_kernel<<<(NN * 4 + 255) / 256, 256>>>(p_s, NN * 4);
    zero_kernel<<<(NN * 128 + 255) / 256, 256>>>(p_acc, NN * 128);
    edge_kernel<<<NE / 8, 256>>>(ei, p_nq, p_e, p_s, p_acc);
    norm_kernel<<<(NN * 32 + 255) / 256, 256>>>(p_nq, p_acc, p_s, p_x, 1);

    // ----- layer 2 -----
    concat_w<<<(128 * 512) / 256, 256>>>(q2W, k2W, v2W, s2W, q2b, k2b, v2b, s2b);
    gemm_tf32<float><<<dim3(GB_N, 4), 256>>>(p_x, p_Wc, p_bc, p_nq, NN, 128, 512);
    gemm_tf32<__half><<<dim3(GB_E, 1), 256>>>(p_attr, e2W, nullptr, p_e, NE, 64, 128);
    zero_kernel<<<(NN * 4 + 255) / 256, 256>>>(p_s, NN * 4);
    zero_kernel<<<(NN * 128 + 255) / 256, 256>>>(p_acc, NN * 128);
    edge_kernel<<<NE / 8, 256>>>(ei, p_nq, p_e, p_s, p_acc);
    norm_kernel<<<(NN * 32 + 255) / 256, 256>>>(p_nq, p_acc, p_s, p_h2, 0);

    // ----- projection -----
    proj_kernel<<<(BATCH + 7) / 8, 256>>>(p_h2, pW, pb, (float*)d_out);
}

// round 4
// speedup vs baseline: 2.5617x; 1.3043x over previous
#include <cuda_runtime.h>
#include <cuda_fp16.h>
#include <math.h>

#define NN 50000
#define NE 500000
#define BATCH 10000

// ---------------- scratch ----------------
__device__ float  g_x[NN * 128];        // fp32 node features (layer input)
__device__ __half g_qkvh[NN * 384];     // fp16 [q|k|v]
__device__ float  g_skip[NN * 128];     // fp32 skip
__device__ float  g_acc[NN * 128];
__device__ __half g_e[NE * 128];
__device__ float  g_s[NN * 4];
__device__ float  g_h2[NN * 128];
__device__ float  g_Wc[128 * 512];
__device__ float  g_bc[512];
__device__ int    g_eidx[NE];           // layer-2 compacted edge ids
__device__ int    g_cnt;

__device__ __forceinline__ unsigned f2tf(float f) {
    unsigned u;
    asm("cvt.rna.tf32.f32 %0, %1;" : "=r"(u) : "f"(f));
    return u;
}

// ---------------- x = node_emb[n_id] ----------------
__global__ void gather_kernel(const int* __restrict__ n_id,
                              const float* __restrict__ emb) {
    int idx = blockIdx.x * blockDim.x + threadIdx.x;
    if (idx >= NN * 32) return;
    int i = idx >> 5;
    int c = (idx & 31) * 4;
    *(float4*)&g_x[i * 128 + c] = *(const float4*)&emb[n_id[i] * 128 + c];
}

// ---------------- compact edges with dst < BATCH ----------------
__global__ void zero_cnt_kernel() { g_cnt = 0; }
__global__ void compact_kernel(const int* __restrict__ ei) {
    int e = blockIdx.x * blockDim.x + threadIdx.x;
    if (e >= NE) return;
    if (ei[NE + e] < BATCH) {
        int slot = atomicAdd(&g_cnt, 1);
        g_eidx[slot] = e;
    }
}

// ---------------- concat 4x [128,128] weights -> [128,512] ----------------
__global__ void concat_w(const float* __restrict__ qW, const float* __restrict__ kW,
                         const float* __restrict__ vW, const float* __restrict__ sW,
                         const float* __restrict__ qb, const float* __restrict__ kb,
                         const float* __restrict__ vb, const float* __restrict__ sb) {
    int i = blockIdx.x * blockDim.x + threadIdx.x;
    if (i >= 128 * 512) return;
    int k = i >> 9, c = i & 511;
    int which = c >> 7, cc = c & 127;
    const float* W = which == 0 ? qW : which == 1 ? kW : which == 2 ? vW : sW;
    g_Wc[i] = W[k * 128 + cc];
    if (k == 0) {
        const float* b = which == 0 ? qb : which == 1 ? kb : which == 2 ? vb : sb;
        g_bc[c] = b[cc];
    }
}

// ---------------- node GEMM: [q|k|v] fp16 + skip fp32 -----------------------
// C[M,512] = A[M,128] @ Wc[128,512] + bc ; tile 128x128, BK=32, 256 thr
__global__ __launch_bounds__(256) void node_gemm(
    const float* __restrict__ A, const float* __restrict__ W,
    const float* __restrict__ bias, __half* __restrict__ Cq,
    float* __restrict__ Cs, int M) {
    __shared__ unsigned As[32][136];
    __shared__ unsigned Bs[32][136];
    const int tid = threadIdx.x;
    const int lane = tid & 31, wid = tid >> 5;
    const int wm = (wid & 3) * 32, wn = (wid >> 2) * 64;
    const int g = lane >> 2, t = lane & 3;
    const int m0 = blockIdx.x * 128;
    const int n0 = blockIdx.y * 128;

    float acc[2][8][4];
#pragma unroll
    for (int i = 0; i < 2; i++)
#pragma unroll
        for (int j = 0; j < 8; j++)
#pragma unroll
            for (int c = 0; c < 4; c++) acc[i][j][c] = 0.f;

    const int arow = tid >> 1, acol = (tid & 1) * 16;
    const int brow = tid >> 3, bcol = (tid & 7) * 16;

    for (int k0 = 0; k0 < 128; k0 += 32) {
        int gr = m0 + arow;
        const float* ap = &A[(size_t)gr * 128 + k0 + acol];
#pragma unroll
        for (int c = 0; c < 4; c++) {
            float4 v = (gr < M) ? *(const float4*)(ap + c * 4)
                                : make_float4(0.f, 0.f, 0.f, 0.f);
            As[acol + c * 4 + 0][arow] = f2tf(v.x);
            As[acol + c * 4 + 1][arow] = f2tf(v.y);
            As[acol + c * 4 + 2][arow] = f2tf(v.z);
            As[acol + c * 4 + 3][arow] = f2tf(v.w);
        }
        const float* wp = &W[(size_t)(k0 + brow) * 512 + n0 + bcol];
#pragma unroll
        for (int c = 0; c < 4; c++) {
            float4 v = *(const float4*)(wp + c * 4);
            Bs[brow][bcol + c * 4 + 0] = f2tf(v.x);
            Bs[brow][bcol + c * 4 + 1] = f2tf(v.y);
            Bs[brow][bcol + c * 4 + 2] = f2tf(v.z);
            Bs[brow][bcol + c * 4 + 3] = f2tf(v.w);
        }
        __syncthreads();
#pragma unroll
        for (int kk = 0; kk < 32; kk += 8) {
            unsigned af[2][4];
#pragma unroll
            for (int i = 0; i < 2; i++) {
                af[i][0] = As[kk + t][wm + i * 16 + g];
                af[i][1] = As[kk + t][wm + i * 16 + g + 8];
                af[i][2] = As[kk + t + 4][wm + i * 16 + g];
                af[i][3] = As[kk + t + 4][wm + i * 16 + g + 8];
            }
            unsigned bf[8][2];
#pragma unroll
            for (int j = 0; j < 8; j++) {
                bf[j][0] = Bs[kk + t][wn + j * 8 + g];
                bf[j][1] = Bs[kk + t + 4][wn + j * 8 + g];
            }
#pragma unroll
            for (int i = 0; i < 2; i++)
#pragma unroll
                for (int j = 0; j < 8; j++) {
                    float* c = acc[i][j];
                    asm volatile(
                        "mma.sync.aligned.m16n8k8.row.col.f32.tf32.tf32.f32 "
                        "{%0,%1,%2,%3}, {%4,%5,%6,%7}, {%8,%9}, {%0,%1,%2,%3};"
                        : "+f"(c[0]), "+f"(c[1]), "+f"(c[2]), "+f"(c[3])
                        : "r"(af[i][0]), "r"(af[i][1]), "r"(af[i][2]),
                          "r"(af[i][3]), "r"(bf[j][0]), "r"(bf[j][1]));
                }
        }
        __syncthreads();
    }
#pragma unroll
    for (int i = 0; i < 2; i++) {
        int r0 = m0 + wm + i * 16 + g;
#pragma unroll
        for (int j = 0; j < 8; j++) {
            int col = n0 + wn + j * 8 + t * 2;
            float b0 = bias[col], b1 = bias[col + 1];
#pragma unroll
            for (int rr = 0; rr < 2; rr++) {
                int row = r0 + rr * 8;
                if (row < M) {
                    float o0 = acc[i][j][rr * 2 + 0] + b0;
                    float o1 = acc[i][j][rr * 2 + 1] + b1;
                    if (n0 < 384) {
                        *(__half2*)&Cq[(size_t)row * 384 + col] =
                            __floats2half2_rn(o0, o1);
                    } else {
                        *(float2*)&Cs[(size_t)row * 128 + col - 384] =
                            make_float2(o0, o1);
                    }
                }
            }
        }
    }
}

// -------- fused attr+edge GEMM: E[e,:] = [feats(e)|cos(t*tw+tb)] @ We --------
// K=64, N=128; A tile built in-kernel. eidx==null -> identity edge list.
__global__ __launch_bounds__(256) void edge_gemm(
    const float* __restrict__ feats, const float* __restrict__ times,
    const float* __restrict__ tw, const float* __restrict__ tb,
    const float* __restrict__ We,
    const int* __restrict__ eidx, const int* __restrict__ cntp, int cnt_c,
    __half* __restrict__ E) {
    const int cnt = cntp ? *cntp : cnt_c;
    const int m0 = blockIdx.x * 128;
    if (m0 >= cnt) return;
    __shared__ unsigned As[32][136];
    __shared__ unsigned Bs[32][136];
    const int tid = threadIdx.x;
    const int lane = tid & 31, wid = tid >> 5;
    const int wm = (wid & 3) * 32, wn = (wid >> 2) * 64;
    const int g = lane >> 2, t = lane & 3;

    float acc[2][8][4];
#pragma unroll
    for (int i = 0; i < 2; i++)
#pragma unroll
        for (int j = 0; j < 8; j++)
#pragma unroll
            for (int c = 0; c < 4; c++) acc[i][j][c] = 0.f;

    const int arow = tid >> 1, acol = (tid & 1) * 16;
    const int brow = tid >> 3, bcol = (tid & 7) * 16;

    for (int k0 = 0; k0 < 64; k0 += 32) {
        int r = m0 + arow;
        bool valid = r < cnt;
        int eid = valid ? (eidx ? eidx[r] : r) : 0;
        if (k0 == 0) {  // feats columns 0..31
            const float* ap = &feats[(size_t)eid * 32 + acol];
#pragma unroll
            for (int c = 0; c < 4; c++) {
                float4 v = valid ? *(const float4*)(ap + c * 4)
                                 : make_float4(0.f, 0.f, 0.f, 0.f);
                As[acol + c * 4 + 0][arow] = f2tf(v.x);
                As[acol + c * 4 + 1][arow] = f2tf(v.y);
                As[acol + c * 4 + 2][arow] = f2tf(v.z);
                As[acol + c * 4 + 3][arow] = f2tf(v.w);
            }
        } else {        // time-embedding columns 32..63
            float tv = valid ? times[eid] : 0.f;
#pragma unroll
            for (int c = 0; c < 16; c++) {
                int j = acol + c;                 // 0..31
                float cv = valid ? cosf(tv * __ldg(&tw[j]) + __ldg(&tb[j])) : 0.f;
                As[j][arow] = f2tf(cv);
            }
        }
        const float* wp = &We[(size_t)(k0 + brow) * 128 + bcol];
#pragma unroll
        for (int c = 0; c < 4; c++) {
            float4 v = *(const float4*)(wp + c * 4);
            Bs[brow][bcol + c * 4 + 0] = f2tf(v.x);
            Bs[brow][bcol + c * 4 + 1] = f2tf(v.y);
            Bs[brow][bcol + c * 4 + 2] = f2tf(v.z);
            Bs[brow][bcol + c * 4 + 3] = f2tf(v.w);
        }
        __syncthreads();
#pragma unroll
        for (int kk = 0; kk < 32; kk += 8) {
            unsigned af[2][4];
#pragma unroll
            for (int i = 0; i < 2; i++) {
                af[i][0] = As[kk + t][wm + i * 16 + g];
                af[i][1] = As[kk + t][wm + i * 16 + g + 8];
                af[i][2] = As[kk + t + 4][wm + i * 16 + g];
                af[i][3] = As[kk + t + 4][wm + i * 16 + g + 8];
            }
            unsigned bf[8][2];
#pragma unroll
            for (int j = 0; j < 8; j++) {
                bf[j][0] = Bs[kk + t][wn + j * 8 + g];
                bf[j][1] = Bs[kk + t + 4][wn + j * 8 + g];
            }
#pragma unroll
            for (int i = 0; i < 2; i++)
#pragma unroll
                for (int j = 0; j < 8; j++) {
                    float* c = acc[i][j];
                    asm volatile(
                        "mma.sync.aligned.m16n8k8.row.col.f32.tf32.tf32.f32 "
                        "{%0,%1,%2,%3}, {%4,%5,%6,%7}, {%8,%9}, {%0,%1,%2,%3};"
                        : "+f"(c[0]), "+f"(c[1]), "+f"(c[2]), "+f"(c[3])
                        : "r"(af[i][0]), "r"(af[i][1]), "r"(af[i][2]),
                          "r"(af[i][3]), "r"(bf[j][0]), "r"(bf[j][1]));
                }
        }
        __syncthreads();
    }
#pragma unroll
    for (int i = 0; i < 2; i++) {
        int r0 = m0 + wm + i * 16 + g;
#pragma unroll
        for (int j = 0; j < 8; j++) {
            int col = wn + j * 8 + t * 2;
#pragma unroll
            for (int rr = 0; rr < 2; rr++) {
                int row = r0 + rr * 8;
                if (row < cnt)
                    *(__half2*)&E[(size_t)row * 128 + col] = __floats2half2_rn(
                        acc[i][j][rr * 2 + 0], acc[i][j][rr * 2 + 1]);
            }
        }
    }
}

// ---------------- zero ----------------
__global__ void zero_kernel(float* p, int n) {
    int i = blockIdx.x * blockDim.x + threadIdx.x;
    if (i < n) p[i] = 0.f;
}

// ------- fused edge pass -------
__global__ void edge_kernel(const int* __restrict__ ei,
                            const __half* __restrict__ qkv,
                            const __half* __restrict__ e,
                            const int* __restrict__ eidx,
                            const int* __restrict__ cntp, int cnt_c,
                            float* __restrict__ s,
                            float* __restrict__ acc) {
    int cnt = cntp ? *cntp : cnt_c;
    int w = (blockIdx.x * blockDim.x + threadIdx.x) >> 5;
    int lane = threadIdx.x & 31;
    if (w >= cnt) return;
    int eid = eidx ? eidx[w] : w;
    int src = ei[eid], dst = ei[NE + eid];
    uint2 eraw = *(const uint2*)&e[(size_t)w * 128 + lane * 4];
    float2 e01 = __half22float2(*reinterpret_cast<__half2*>(&eraw.x));
    float2 e23 = __half22float2(*reinterpret_cast<__half2*>(&eraw.y));
    uint2 qraw = *(const uint2*)&qkv[(size_t)dst * 384 + lane * 4];
    uint2 kraw = *(const uint2*)&qkv[(size_t)src * 384 + 128 + lane * 4];
    uint2 vraw = *(const uint2*)&qkv[(size_t)src * 384 + 256 + lane * 4];
    float2 q01 = __half22float2(*reinterpret_cast<__half2*>(&qraw.x));
    float2 q23 = __half22float2(*reinterpret_cast<__half2*>(&qraw.y));
    float2 k01 = __half22float2(*reinterpret_cast<__half2*>(&kraw.x));
    float2 k23 = __half22float2(*reinterpret_cast<__half2*>(&kraw.y));
    float2 v01 = __half22float2(*reinterpret_cast<__half2*>(&vraw.x));
    float2 v23 = __half22float2(*reinterpret_cast<__half2*>(&vraw.y));
    float p = q01.x * (k01.x + e01.x) + q01.y * (k01.y + e01.y) +
              q23.x * (k23.x + e23.x) + q23.y * (k23.y + e23.y);
    p += __shfl_xor_sync(0xffffffffu, p, 1, 8);
    p += __shfl_xor_sync(0xffffffffu, p, 2, 8);
    p += __shfl_xor_sync(0xffffffffu, p, 4, 8);
    float a = expf(p * 0.17677669529663687f);   // 1/sqrt(32)
    if ((lane & 7) == 0)
        atomicAdd(&s[dst * 4 + (lane >> 3)], a);
    float4 m = make_float4(a * (v01.x + e01.x), a * (v01.y + e01.y),
                           a * (v23.x + e23.x), a * (v23.y + e23.y));
    float* op = &acc[(size_t)dst * 128 + lane * 4];
    asm volatile("red.global.add.v4.f32 [%0], {%1,%2,%3,%4};"
                 :: "l"(op), "f"(m.x), "f"(m.y), "f"(m.z), "f"(m.w)
                 : "memory");
}

// ------- normalize: out = skip + acc/s (+relu) -------
__global__ void norm_kernel(const float* __restrict__ skip,
                            const float* __restrict__ acc,
                            const float* __restrict__ s,
                            float* __restrict__ outp, int nrows, int do_relu) {
    int idx = blockIdx.x * blockDim.x + threadIdx.x;
    if (idx >= nrows * 32) return;
    int n = idx >> 5, c4 = idx & 31;
    float inv = 1.f / (s[n * 4 + (c4 >> 3)] + 1e-16f);
    float4 a = *(const float4*)&acc[n * 128 + c4 * 4];
    float4 kk = *(const float4*)&skip[(size_t)n * 128 + c4 * 4];
    float4 o = make_float4(kk.x + a.x * inv, kk.y + a.y * inv,
                           kk.z + a.z * inv, kk.w + a.w * inv);
    if (do_relu) {
        o.x = fmaxf(o.x, 0.f); o.y = fmaxf(o.y, 0.f);
        o.z = fmaxf(o.z, 0.f); o.w = fmaxf(o.w, 0.f);
    }
    *(float4*)&outp[n * 128 + c4 * 4] = o;
}

// ---------------- final projection ----------------
__global__ void proj_kernel(const float* __restrict__ x,
                            const float* __restrict__ pW,
                            const float* __restrict__ pb,
                            float* __restrict__ y) {
    int row = blockIdx.x * 8 + (threadIdx.x >> 5);
    int lane = threadIdx.x & 31;
    if (row >= BATCH) return;
    float acc = pb[lane];
    const float* xr = &x[row * 128];
#pragma unroll 8
    for (int k = 0; k < 128; k++) acc += xr[k] * pW[k * 32 + lane];
    y[row * 32 + lane] = acc;
}

// ---------------- host launch ----------------
extern "C" void kernel_launch(void* const* d_in, const int* in_sizes, int n_in,
                              void* d_out, int out_size) {
    int off = (n_in >= 28) ? 1 : 0;
    const int* n_id       = (const int*)d_in[0];
    const int* ei         = (const int*)d_in[1];
    const float* times    = (const float*)d_in[2];
    const float* feats    = (const float*)d_in[3];
    const float* node_emb = (const float*)d_in[4 + off];
    const float* tw       = (const float*)d_in[5 + off];
    const float* tb       = (const float*)d_in[6 + off];
    const float* q1W = (const float*)d_in[7 + off],  *q1b = (const float*)d_in[8 + off];
    const float* k1W = (const float*)d_in[9 + off],  *k1b = (const float*)d_in[10 + off];
    const float* v1W = (const float*)d_in[11 + off], *v1b = (const float*)d_in[12 + off];
    const float* e1W = (const float*)d_in[13 + off];
    const float* s1W = (const float*)d_in[14 + off], *s1b = (const float*)d_in[15 + off];
    const float* q2W = (const float*)d_in[16 + off], *q2b = (const float*)d_in[17 + off];
    const float* k2W = (const float*)d_in[18 + off], *k2b = (const float*)d_in[19 + off];
    const float* v2W = (const float*)d_in[20 + off], *v2b = (const float*)d_in[21 + off];
    const float* e2W = (const float*)d_in[22 + off];
    const float* s2W = (const float*)d_in[23 + off], *s2b = (const float*)d_in[24 + off];
    const float* pW  = (const float*)d_in[25 + off], *pb  = (const float*)d_in[26 + off];

    float *p_x, *p_skip, *p_acc, *p_s, *p_h2, *p_Wc, *p_bc;
    __half *p_e, *p_qkv;
    int *p_eidx, *p_cnt;
    cudaGetSymbolAddress((void**)&p_x, g_x);
    cudaGetSymbolAddress((void**)&p_qkv, g_qkvh);
    cudaGetSymbolAddress((void**)&p_skip, g_skip);
    cudaGetSymbolAddress((void**)&p_acc, g_acc);
    cudaGetSymbolAddress((void**)&p_e, g_e);
    cudaGetSymbolAddress((void**)&p_s, g_s);
    cudaGetSymbolAddress((void**)&p_h2, g_h2);
    cudaGetSymbolAddress((void**)&p_Wc, g_Wc);
    cudaGetSymbolAddress((void**)&p_bc, g_bc);
    cudaGetSymbolAddress((void**)&p_eidx, g_eidx);
    cudaGetSymbolAddress((void**)&p_cnt, g_cnt);

    const int GB_N = (NN + 127) / 128;    // 391
    const int GB_E = (NE + 127) / 128;    // 3907

    zero_cnt_kernel<<<1, 1>>>();
    compact_kernel<<<(NE + 255) / 256, 256>>>(ei);
    gather_kernel<<<(NN * 32) / 256, 256>>>(n_id, node_emb);

    // ----- layer 1 (all nodes, all edges) -----
    concat_w<<<(128 * 512) / 256, 256>>>(q1W, k1W, v1W, s1W, q1b, k1b, v1b, s1b);
    node_gemm<<<dim3(GB_N, 4), 256>>>(p_x, p_Wc, p_bc, p_qkv, p_skip, NN);
    edge_gemm<<<GB_E, 256>>>(feats, times, tw, tb, e1W, nullptr, nullptr, NE, p_e);
    zero_kernel<<<(NN * 4 + 255) / 256, 256>>>(p_s, NN * 4);
    zero_kernel<<<(NN * 128 + 255) / 256, 256>>>(p_acc, NN * 128);
    edge_kernel<<<NE / 8, 256>>>(ei, p_qkv, p_e, nullptr, nullptr, NE, p_s, p_acc);
    norm_kernel<<<(NN * 32 + 255) / 256, 256>>>(p_skip, p_acc, p_s, p_x, NN, 1);

    // ----- layer 2 (only edges with dst < BATCH matter) -----
    concat_w<<<(128 * 512) / 256, 256>>>(q2W, k2W, v2W, s2W, q2b, k2b, v2b, s2b);
    node_gemm<<<dim3(GB_N, 4), 256>>>(p_x, p_Wc, p_bc, p_qkv, p_skip, NN);
    edge_gemm<<<GB_E, 256>>>(feats, times, tw, tb, e2W, p_eidx, p_cnt, 0, p_e);
    zero_kernel<<<(BATCH * 4 + 255) / 256, 256>>>(p_s, BATCH * 4);
    zero_kernel<<<(BATCH * 128 + 255) / 256, 256>>>(p_acc, BATCH * 128);
    edge_kernel<<<NE / 8, 256>>>(ei, p_qkv, p_e, p_eidx, p_cnt, 0, p_s, p_acc);
    norm_kernel<<<(BATCH * 32 + 255) / 256, 256>>>(p_skip, p_acc, p_s, p_h2, BATCH, 0);

    // ----- projection -----
    proj_kernel<<<(BATCH + 7) / 8, 256>>>(p_h2, pW, pb, (float*)d_out);
}